// round 16
// baseline (speedup 1.0000x reference)
#include <cuda_runtime.h>
#include <cuda_fp16.h>
#include <cstdint>

// out[b,n,m] = sum_d x1[b,n,d]*x2[b,m,d] + const   (B=4, N=M=4096, D=32, fp32)
//
// Round 16: fp16 mma (m16n8k16). Same 11-bit significand as tf32 -> rel_err
// ~3e-4, but smem tiles HALVE -> mainloop LDS wavefronts halve (512->256/CTA),
// mma+LDS instruction count halves. Staging: LDG.128 + cvt(half2) + 2x STS.32.
//
// Layout (bank-proofs in round notes):
//  - row = 16 words (32 halves); unit u (k-pair) at word p(u)^swz(row),
//    p(u)=2*(u&3)+((u>>2)&1)+8*(u>>3), swz=10*((row>>1)&1)  [bits 1+3]
//  - staging STS.32 conflict-free (B iterates SLOTS; gmem row = bperm(slot))
//  - mainloop LDS.64 at word (8j+2t4)^(10*sg), sg=(g>>1)&1: conflict-free,
//    yields (a0,a2)/(a1,a3)/(b0,b1) pairs directly.
//  - bperm'd B -> contiguous STG.128 epilogue with __stcs (as R12).
//  - 8192 CTAs, 256 thr, 4 CTAs/SM.

#define TILE_M 128
#define TILE_N 64
#define DDIM 32
#define A_WORDS (TILE_M * 16)       // 2048 words, 8KB
#define B_WORDS (TILE_N * 16)       // 1024 words, 4KB

__device__ __forceinline__ uint32_t pack_half2(float lo, float hi) {
    uint32_t w;
    asm("cvt.rn.f16x2.f32 %0, %1, %2;" : "=r"(w) : "f"(hi), "f"(lo));
    return w;
}

__device__ __forceinline__ void mma_f16_16x8x16(
    float& d0, float& d1, float& d2, float& d3,
    uint32_t a0, uint32_t a1, uint32_t a2, uint32_t a3,
    uint32_t b0, uint32_t b1) {
    asm volatile(
        "mma.sync.aligned.m16n8k16.row.col.f32.f16.f16.f32 "
        "{%0,%1,%2,%3}, {%4,%5,%6,%7}, {%8,%9}, {%0,%1,%2,%3};"
        : "+f"(d0), "+f"(d1), "+f"(d2), "+f"(d3)
        : "r"(a0), "r"(a1), "r"(a2), "r"(a3), "r"(b0), "r"(b1));
}

// B row permutation (involution): within each 32-block, r = 8b+2a+e -> 8a+2b+e.
// Makes mma frag col (8nt+2t4+e) correspond to gmem col (8t4+2nt+e).
__device__ __forceinline__ int bperm(int r) {
    int blk = r & ~31;
    int u = r & 31;
    int a = u >> 3, bb = (u & 7) >> 1, e = u & 1;
    return blk + (bb << 3) + (a << 1) + e;
}

// Position of k-pair unit u within a 16-word row (pre-swizzle).
__device__ __forceinline__ int unit_pos(int u) {
    return 2 * (u & 3) + ((u >> 2) & 1) + 8 * (u >> 3);
}

__global__ __launch_bounds__(256, 4)
void bmm_mma_kernel(const float* __restrict__ x1,
                    const float* __restrict__ x2,
                    const float* __restrict__ cptr,
                    float* __restrict__ out) {
    __shared__ uint32_t As[A_WORDS];
    __shared__ uint32_t Bs[B_WORDS];

    const int tid = threadIdx.x;
    const int wid = tid >> 5;
    const int lid = tid & 31;
    const int g   = lid >> 2;     // groupID 0..7
    const int t4  = lid & 3;      // thread-in-group 0..3
    const int warp_m = wid & 3;   // 0..3  (32-row block)
    const int warp_n = wid >> 2;  // 0..1  (32-col block)
    const int b = blockIdx.z;
    const int N = 4096, M = 4096;

    // ---- Stage A: LDG.128 -> 2x half2 -> 2x STS.32 (conflict-free) ----
    const float* a_base = x1 + ((size_t)b * N + (size_t)blockIdx.y * TILE_M) * DDIM;
    #pragma unroll
    for (int i = 0; i < 4; i++) {
        int s = tid + i * 256;        // 0..1023
        int row = s >> 3;
        int q   = s & 7;
        float4 v = *(const float4*)(a_base + (size_t)row * DDIM + q * 4);
        int P = unit_pos(2 * q) ^ (10 * ((row >> 1) & 1));
        As[row * 16 + P]       = pack_half2(v.x, v.y);   // unit 2q
        As[row * 16 + (P ^ 2)] = pack_half2(v.z, v.w);   // unit 2q+1 (p+2)
    }
    // ---- Stage B: iterate SLOTS (gmem row = bperm(slot)) ----
    const float* b_base = x2 + ((size_t)b * M + (size_t)blockIdx.x * TILE_N) * DDIM;
    #pragma unroll
    for (int i = 0; i < 2; i++) {
        int s = tid + i * 256;        // 0..511
        int slot = s >> 3;
        int q    = s & 7;
        int grow = bperm(slot);
        float4 v = *(const float4*)(b_base + (size_t)grow * DDIM + q * 4);
        int P = unit_pos(2 * q) ^ (10 * ((slot >> 1) & 1));
        Bs[slot * 16 + P]       = pack_half2(v.x, v.y);
        Bs[slot * 16 + (P ^ 2)] = pack_half2(v.z, v.w);
    }
    const float cbias = cptr[0];
    __syncthreads();

    // ---- MMA mainloop: 2 k-steps of 16 ----
    float acc[2][4][4];
    #pragma unroll
    for (int mt = 0; mt < 2; mt++)
        #pragma unroll
        for (int nt = 0; nt < 4; nt++)
            #pragma unroll
            for (int r = 0; r < 4; r++)
                acc[mt][nt][r] = 0.0f;

    const int sg = (g >> 1) & 1;
    const int swzw = 10 * sg;
    const int arow0 = warp_m * 32 + g;
    const int brow0 = warp_n * 32 + g;
    #pragma unroll
    for (int j = 0; j < 2; j++) {
        const int w = (8 * j + 2 * t4) ^ swzw;   // even -> 8B-aligned pair
        // A: uint2 = (unit 8j+t4, unit 8j+t4+4) = (a0,a2) for row, (a1,a3) row+8
        uint2 va[2][2];
        #pragma unroll
        for (int mt = 0; mt < 2; mt++) {
            int r0 = arow0 + mt * 16;
            va[mt][0] = *(const uint2*)&As[r0 * 16 + w];
            va[mt][1] = *(const uint2*)&As[(r0 + 8) * 16 + w];
        }
        uint2 vb[4];
        #pragma unroll
        for (int nt = 0; nt < 4; nt++)
            vb[nt] = *(const uint2*)&Bs[(brow0 + nt * 8) * 16 + w];

        #pragma unroll
        for (int mt = 0; mt < 2; mt++)
            #pragma unroll
            for (int nt = 0; nt < 4; nt++)
                mma_f16_16x8x16(acc[mt][nt][0], acc[mt][nt][1],
                                acc[mt][nt][2], acc[mt][nt][3],
                                va[mt][0].x, va[mt][1].x,
                                va[mt][0].y, va[mt][1].y,
                                vb[nt].x, vb[nt].y);
    }

    // ---- Epilogue: contiguous streaming stores (identical to R12) ----
    const size_t row_base = (size_t)b * N + (size_t)blockIdx.y * TILE_M + warp_m * 32;
    const size_t col0 = (size_t)blockIdx.x * TILE_N + warp_n * 32 + 8 * t4;
    #pragma unroll
    for (int mt = 0; mt < 2; mt++) {
        size_t r0 = row_base + mt * 16 + g;
        float* p0 = out + r0 * M + col0;         // row g
        float* p1 = out + (r0 + 8) * M + col0;   // row g+8
        float4 v;
        v = make_float4(acc[mt][0][0] + cbias, acc[mt][0][1] + cbias,
                        acc[mt][1][0] + cbias, acc[mt][1][1] + cbias);
        __stcs((float4*)(p0), v);
        v = make_float4(acc[mt][2][0] + cbias, acc[mt][2][1] + cbias,
                        acc[mt][3][0] + cbias, acc[mt][3][1] + cbias);
        __stcs((float4*)(p0 + 4), v);
        v = make_float4(acc[mt][0][2] + cbias, acc[mt][0][3] + cbias,
                        acc[mt][1][2] + cbias, acc[mt][1][3] + cbias);
        __stcs((float4*)(p1), v);
        v = make_float4(acc[mt][2][2] + cbias, acc[mt][2][3] + cbias,
                        acc[mt][3][2] + cbias, acc[mt][3][3] + cbias);
        __stcs((float4*)(p1 + 4), v);
    }
}

extern "C" void kernel_launch(void* const* d_in, const int* in_sizes, int n_in,
                              void* d_out, int out_size) {
    const float* x1  = (const float*)d_in[0];   // [4, 4096, 32]
    const float* x2  = (const float*)d_in[1];   // [4, 4096, 32]
    const float* cst = (const float*)d_in[2];   // [1]
    float* out       = (float*)d_out;           // [4, 4096, 4096]

    dim3 grid(4096 / TILE_N, 4096 / TILE_M, 4);   // 64 x 32 x 4 = 8192
    bmm_mma_kernel<<<grid, 256>>>(x1, x2, cst, out);
}

// round 17
// speedup vs baseline: 1.1207x; 1.1207x over previous
#include <cuda_runtime.h>
#include <cuda_fp16.h>
#include <cstdint>

// out[b,n,m] = sum_d x1[b,n,d]*x2[b,m,d] + const   (B=4, N=M=4096, D=32, fp32)
//
// Round 17: fp16 mma, 64x64 tile, 128-thread CTAs, 8 CTAs/SM.
// Diagnosis: kernel is phase-LATENCY bound (74-76us across all instruction
// mixes). Fix: double the independent CTAs per SM (8 chains in flight) and
// quarter the barrier width (4 warps). Per-warp machinery identical to R16:
//  - half2 unit u at word p(u)^swz(row), p(u)=2*(u&3)+((u>>2)&1)+8*(u>>3),
//    swz=10*((row>>1)&1); staging STS.32 and mainloop LDS.64 conflict-free
//  - bperm'd B rows -> contiguous STG.128 epilogue with __stcs
//  - 16384 CTAs (64x64x4 grid)

#define TILE_M 64
#define TILE_N 64
#define DDIM 32
#define A_WORDS (TILE_M * 16)       // 1024 words, 4KB
#define B_WORDS (TILE_N * 16)       // 1024 words, 4KB

__device__ __forceinline__ uint32_t pack_half2(float lo, float hi) {
    uint32_t w;
    asm("cvt.rn.f16x2.f32 %0, %1, %2;" : "=r"(w) : "f"(hi), "f"(lo));
    return w;
}

__device__ __forceinline__ void mma_f16_16x8x16(
    float& d0, float& d1, float& d2, float& d3,
    uint32_t a0, uint32_t a1, uint32_t a2, uint32_t a3,
    uint32_t b0, uint32_t b1) {
    asm volatile(
        "mma.sync.aligned.m16n8k16.row.col.f32.f16.f16.f32 "
        "{%0,%1,%2,%3}, {%4,%5,%6,%7}, {%8,%9}, {%0,%1,%2,%3};"
        : "+f"(d0), "+f"(d1), "+f"(d2), "+f"(d3)
        : "r"(a0), "r"(a1), "r"(a2), "r"(a3), "r"(b0), "r"(b1));
}

// B row permutation (involution): within each 32-block, r = 8b+2a+e -> 8a+2b+e.
// Makes mma frag col (8nt+2t4+e) correspond to gmem col (8t4+2nt+e).
__device__ __forceinline__ int bperm(int r) {
    int blk = r & ~31;
    int u = r & 31;
    int a = u >> 3, bb = (u & 7) >> 1, e = u & 1;
    return blk + (bb << 3) + (a << 1) + e;
}

// Position of k-pair unit u within a 16-word row (pre-swizzle).
__device__ __forceinline__ int unit_pos(int u) {
    return 2 * (u & 3) + ((u >> 2) & 1) + 8 * (u >> 3);
}

__global__ __launch_bounds__(128, 8)
void bmm_mma_kernel(const float* __restrict__ x1,
                    const float* __restrict__ x2,
                    const float* __restrict__ cptr,
                    float* __restrict__ out) {
    __shared__ uint32_t As[A_WORDS];
    __shared__ uint32_t Bs[B_WORDS];

    const int tid = threadIdx.x;
    const int wid = tid >> 5;
    const int lid = tid & 31;
    const int g   = lid >> 2;     // groupID 0..7
    const int t4  = lid & 3;      // thread-in-group 0..3
    const int warp_m = wid & 1;   // 0..1  (32-row block)
    const int warp_n = wid >> 1;  // 0..1  (32-col block)
    const int b = blockIdx.z;
    const int N = 4096, M = 4096;

    // ---- Stage A: LDG.128 -> 2x half2 -> 2x STS.32 (conflict-free) ----
    const float* a_base = x1 + ((size_t)b * N + (size_t)blockIdx.y * TILE_M) * DDIM;
    #pragma unroll
    for (int i = 0; i < 4; i++) {
        int s = tid + i * 128;        // 0..511
        int row = s >> 3;             // 0..63
        int q   = s & 7;
        float4 v = *(const float4*)(a_base + (size_t)row * DDIM + q * 4);
        int P = unit_pos(2 * q) ^ (10 * ((row >> 1) & 1));
        As[row * 16 + P]       = pack_half2(v.x, v.y);   // unit 2q
        As[row * 16 + (P ^ 2)] = pack_half2(v.z, v.w);   // unit 2q+1
    }
    // ---- Stage B: iterate SLOTS (gmem row = bperm(slot)) ----
    const float* b_base = x2 + ((size_t)b * M + (size_t)blockIdx.x * TILE_N) * DDIM;
    #pragma unroll
    for (int i = 0; i < 4; i++) {
        int s = tid + i * 128;        // 0..511
        int slot = s >> 3;            // 0..63
        int q    = s & 7;
        int grow = bperm(slot);
        float4 v = *(const float4*)(b_base + (size_t)grow * DDIM + q * 4);
        int P = unit_pos(2 * q) ^ (10 * ((slot >> 1) & 1));
        Bs[slot * 16 + P]       = pack_half2(v.x, v.y);
        Bs[slot * 16 + (P ^ 2)] = pack_half2(v.z, v.w);
    }
    const float cbias = cptr[0];
    __syncthreads();

    // ---- MMA mainloop: 2 k-steps of 16 ----
    float acc[2][4][4];
    #pragma unroll
    for (int mt = 0; mt < 2; mt++)
        #pragma unroll
        for (int nt = 0; nt < 4; nt++)
            #pragma unroll
            for (int r = 0; r < 4; r++)
                acc[mt][nt][r] = 0.0f;

    const int sg = (g >> 1) & 1;
    const int swzw = 10 * sg;
    const int arow0 = warp_m * 32 + g;
    const int brow0 = warp_n * 32 + g;
    #pragma unroll
    for (int j = 0; j < 2; j++) {
        const int w = (8 * j + 2 * t4) ^ swzw;   // even -> 8B-aligned pair
        uint2 va[2][2];
        #pragma unroll
        for (int mt = 0; mt < 2; mt++) {
            int r0 = arow0 + mt * 16;
            va[mt][0] = *(const uint2*)&As[r0 * 16 + w];
            va[mt][1] = *(const uint2*)&As[(r0 + 8) * 16 + w];
        }
        uint2 vb[4];
        #pragma unroll
        for (int nt = 0; nt < 4; nt++)
            vb[nt] = *(const uint2*)&Bs[(brow0 + nt * 8) * 16 + w];

        #pragma unroll
        for (int mt = 0; mt < 2; mt++)
            #pragma unroll
            for (int nt = 0; nt < 4; nt++)
                mma_f16_16x8x16(acc[mt][nt][0], acc[mt][nt][1],
                                acc[mt][nt][2], acc[mt][nt][3],
                                va[mt][0].x, va[mt][1].x,
                                va[mt][0].y, va[mt][1].y,
                                vb[nt].x, vb[nt].y);
    }

    // ---- Epilogue: contiguous streaming stores ----
    const size_t row_base = (size_t)b * N + (size_t)blockIdx.y * TILE_M + warp_m * 32;
    const size_t col0 = (size_t)blockIdx.x * TILE_N + warp_n * 32 + 8 * t4;
    #pragma unroll
    for (int mt = 0; mt < 2; mt++) {
        size_t r0 = row_base + mt * 16 + g;
        float* p0 = out + r0 * M + col0;         // row g
        float* p1 = out + (r0 + 8) * M + col0;   // row g+8
        float4 v;
        v = make_float4(acc[mt][0][0] + cbias, acc[mt][0][1] + cbias,
                        acc[mt][1][0] + cbias, acc[mt][1][1] + cbias);
        __stcs((float4*)(p0), v);
        v = make_float4(acc[mt][2][0] + cbias, acc[mt][2][1] + cbias,
                        acc[mt][3][0] + cbias, acc[mt][3][1] + cbias);
        __stcs((float4*)(p0 + 4), v);
        v = make_float4(acc[mt][0][2] + cbias, acc[mt][0][3] + cbias,
                        acc[mt][1][2] + cbias, acc[mt][1][3] + cbias);
        __stcs((float4*)(p1), v);
        v = make_float4(acc[mt][2][2] + cbias, acc[mt][2][3] + cbias,
                        acc[mt][3][2] + cbias, acc[mt][3][3] + cbias);
        __stcs((float4*)(p1 + 4), v);
    }
}

extern "C" void kernel_launch(void* const* d_in, const int* in_sizes, int n_in,
                              void* d_out, int out_size) {
    const float* x1  = (const float*)d_in[0];   // [4, 4096, 32]
    const float* x2  = (const float*)d_in[1];   // [4, 4096, 32]
    const float* cst = (const float*)d_in[2];   // [1]
    float* out       = (float*)d_out;           // [4, 4096, 4096]

    dim3 grid(4096 / TILE_N, 4096 / TILE_M, 4);   // 64 x 64 x 4 = 16384
    bmm_mma_kernel<<<grid, 128>>>(x1, x2, cst, out);
}